// round 1
// baseline (speedup 1.0000x reference)
#include <cuda_runtime.h>
#include <cuda_bf16.h>
#include <math.h>

// ---------------------------------------------------------------------------
// Problem constants (structure is fully deterministic from reference code)
// ---------------------------------------------------------------------------
#define BATCH      4096
#define DIM        128
#define NFORM      256
#define NLIT       10752
#define NCONJ      2688

// K1 tiling
#define K1_M       128          // batch rows per CTA
#define K1_N       64           // padded literal columns per CTA
#define K1_TILES   224          // formula-aligned column tiles
// K2 tiling
#define K2_M       128
#define K2_N       64

// Scratch (device globals: no allocation allowed)
__device__ float g_dnnf[BATCH * NFORM];     // out_dnnfs
__device__ float g_loc [BATCH * NFORM];     // exp(-norm) per (b,f)
__device__ float g_A   [DIM * NFORM];       // [k][f] sigma^2
__device__ float g_Bv  [DIM * NFORM];       // [k][f] mu*sigma^2
__device__ float g_c   [NFORM];             // sum_k mu^2 sigma^2

// ---------------------------------------------------------------------------
// K0: precompute sigma^2, mu*sigma^2, c[f]   (one CTA per formula)
// ---------------------------------------------------------------------------
__global__ void k0_precompute(const float* __restrict__ mu,
                              const float* __restrict__ sigma) {
    int f = blockIdx.x;
    int k = threadIdx.x;            // 128 threads
    float sg = sigma[f * DIM + k];
    float m  = mu[f * DIM + k];
    float s2 = sg * sg;
    float bv = m * s2;
    g_A [k * NFORM + f] = s2;
    g_Bv[k * NFORM + f] = bv;
    float cp = m * bv;              // mu^2 sigma^2
    // block reduce (128 = 4 warps)
    #pragma unroll
    for (int off = 16; off > 0; off >>= 1)
        cp += __shfl_xor_sync(0xFFFFFFFFu, cp, off);
    __shared__ float red[4];
    if ((k & 31) == 0) red[k >> 5] = cp;
    __syncthreads();
    if (k == 0) g_c[f] = red[0] + red[1] + red[2] + red[3];
}

// ---------------------------------------------------------------------------
// K1: fused literal GEMM + tanh + conjunction/formula reduction -> g_dnnf
//   grid = (BATCH/128, 224), 256 threads, dynamic smem
//   smem layout: xsT[128][128] (k-major x) | ws[128][64] (k-major W) | bs[64]
//   after the k-loop, xsT region is reused as ct[128][65] (tanh literals)
// ---------------------------------------------------------------------------
#define K1_SMEM_FLOATS (DIM * K1_M + DIM * K1_N + K1_N)
#define K1_SMEM_BYTES  (K1_SMEM_FLOATS * 4)

__global__ __launch_bounds__(256) void k1_literals(
    const float* __restrict__ x, const float* __restrict__ w,
    const float* __restrict__ bias, const float* __restrict__ lm) {

    extern __shared__ __align__(16) float smem[];
    float* xsT = smem;                       // 128*128
    float* ws  = smem + DIM * K1_M;          // 128*64
    float* bs  = ws + DIM * K1_N;            // 64

    const int tile    = blockIdx.y;
    const int rowBase = blockIdx.x * K1_M;
    const int tid     = threadIdx.x;

    // Decode formula-aligned tile
    int g, f0, Lf, litBase, nFt;
    if (tile < 32)        { g = 0; f0 =       2 * tile;       Lf = 24; litBase =        48 * tile;        nFt = 2; }
    else if (tile < 96)   { g = 1; f0 =  64 + (tile - 32);    Lf = 36; litBase = 1536 + 36 * (tile - 32); nFt = 1; }
    else if (tile < 160)  { g = 2; f0 = 128 + (tile - 96);    Lf = 48; litBase = 3840 + 48 * (tile - 96); nFt = 1; }
    else                  { g = 3; f0 = 192 + (tile - 160);   Lf = 60; litBase = 6912 + 60 * (tile - 160);nFt = 1; }
    const int nlit = Lf * nFt;               // 48 / 36 / 48 / 60

    // Load x tile transposed: xsT[k][r]  (128 rows x 128 k)
    for (int e = tid; e < K1_M * (DIM / 4); e += 256) {
        int r  = e >> 5;                     // 32 float4 per row
        int k4 = e & 31;
        float4 v = reinterpret_cast<const float4*>(x + (size_t)(rowBase + r) * DIM)[k4];
        xsT[(k4 * 4 + 0) * K1_M + r] = v.x;
        xsT[(k4 * 4 + 1) * K1_M + r] = v.y;
        xsT[(k4 * 4 + 2) * K1_M + r] = v.z;
        xsT[(k4 * 4 + 3) * K1_M + r] = v.w;
    }
    // Load masked W: ws[k][j], zero-padded to 64 columns
    for (int e = tid; e < DIM * K1_N; e += 256) {
        int k = e >> 6;
        int j = e & 63;
        float wv = 0.f;
        if (j < nlit) {
            int f = f0 + ((j >= Lf) ? 1 : 0);
            float mk = (fabsf(lm[k * NFORM + f]) > 1.0f) ? 1.0f : 0.0f;
            wv = w[(size_t)k * NLIT + litBase + j] * mk;
        }
        ws[e] = wv;
    }
    if (tid < K1_N) bs[tid] = (tid < nlit) ? bias[litBase + tid] : 0.f;
    __syncthreads();

    // Register-tiled GEMM: thread = 8 rows x 4 cols
    const int tx = tid & 15;                 // col group
    const int ty = tid >> 4;                 // row group
    float acc[8][4];
    #pragma unroll
    for (int i = 0; i < 8; ++i)
        #pragma unroll
        for (int j = 0; j < 4; ++j) acc[i][j] = 0.f;

    #pragma unroll 8
    for (int k = 0; k < DIM; ++k) {
        float4 b4 = *reinterpret_cast<const float4*>(&ws[(k << 6) + (tx << 2)]);
        float4 a0 = *reinterpret_cast<const float4*>(&xsT[(k << 7) + (ty << 3)]);
        float4 a1 = *reinterpret_cast<const float4*>(&xsT[(k << 7) + (ty << 3) + 4]);
        float av[8] = {a0.x, a0.y, a0.z, a0.w, a1.x, a1.y, a1.z, a1.w};
        float bv[4] = {b4.x, b4.y, b4.z, b4.w};
        #pragma unroll
        for (int i = 0; i < 8; ++i)
            #pragma unroll
            for (int j = 0; j < 4; ++j)
                acc[i][j] = fmaf(av[i], bv[j], acc[i][j]);
    }
    __syncthreads();   // everyone done reading xsT/ws

    // tanh literals -> ct (reuse xsT region, padded stride 65 vs bank conflicts)
    float* ct = xsT;
    #pragma unroll
    for (int i = 0; i < 8; ++i) {
        int r = ty * 8 + i;
        #pragma unroll
        for (int j = 0; j < 4; ++j) {
            int c = tx * 4 + j;
            ct[r * 65 + c] = tanhf(acc[i][j] + bs[c]);
        }
    }
    __syncthreads();

    // Segmented reduce: nd conjs of each depth {2,4,6}, then formula tanh
    const int nd = 2 + g;                    // conjs per depth
    const float ncf = (float)(6 + 3 * g);    // or_bias
    const int nTasks = K1_M * nFt;
    for (int task = tid; task < nTasks; task += 256) {
        int fi  = task >> 7;
        int row = task & 127;
        int off = fi * Lf;
        const float* cr = &ct[row * 65];
        float fs = 0.f;
        #pragma unroll
        for (int d = 2; d <= 6; d += 2) {
            for (int c = 0; c < nd; ++c) {
                float s = 0.f;
                #pragma unroll 6
                for (int u = 0; u < d; ++u) s += cr[off + u];
                fs += tanhf(s - (float)d + 1.5f);
                off += d;
            }
        }
        g_dnnf[(size_t)(rowBase + row) * NFORM + f0 + fi] = tanhf(fs + ncf - 1.5f);
    }
}

// ---------------------------------------------------------------------------
// K2: loc GEMM:  v(b,f) = sum_k x^2*sig2 - 2*sum_k x*(mu*sig2) + c[f]
//     g_loc = exp(-sqrt(max(v,0)))
//   grid = (32, 4), 256 threads
// ---------------------------------------------------------------------------
#define K2_SMEM_FLOATS (DIM * K2_M + 2 * DIM * K2_N)
#define K2_SMEM_BYTES  (K2_SMEM_FLOATS * 4)

__global__ __launch_bounds__(256) void k2_loc(const float* __restrict__ x) {
    extern __shared__ __align__(16) float smem[];
    float* xsT = smem;                       // 128*128
    float* At  = smem + DIM * K2_M;          // 128*64
    float* Bt  = At + DIM * K2_N;            // 128*64

    const int rowBase = blockIdx.x * K2_M;
    const int fBase   = blockIdx.y * K2_N;
    const int tid     = threadIdx.x;

    for (int e = tid; e < K2_M * (DIM / 4); e += 256) {
        int r  = e >> 5;
        int k4 = e & 31;
        float4 v = reinterpret_cast<const float4*>(x + (size_t)(rowBase + r) * DIM)[k4];
        xsT[(k4 * 4 + 0) * K2_M + r] = v.x;
        xsT[(k4 * 4 + 1) * K2_M + r] = v.y;
        xsT[(k4 * 4 + 2) * K2_M + r] = v.z;
        xsT[(k4 * 4 + 3) * K2_M + r] = v.w;
    }
    for (int e = tid; e < DIM * K2_N; e += 256) {
        int k = e >> 6;
        int j = e & 63;
        At[e] = g_A [k * NFORM + fBase + j];
        Bt[e] = g_Bv[k * NFORM + fBase + j];
    }
    __syncthreads();

    const int tx = tid & 15;
    const int ty = tid >> 4;
    float accA[8][4], accB[8][4];
    #pragma unroll
    for (int i = 0; i < 8; ++i)
        #pragma unroll
        for (int j = 0; j < 4; ++j) { accA[i][j] = 0.f; accB[i][j] = 0.f; }

    #pragma unroll 4
    for (int k = 0; k < DIM; ++k) {
        float4 bA = *reinterpret_cast<const float4*>(&At[(k << 6) + (tx << 2)]);
        float4 bB = *reinterpret_cast<const float4*>(&Bt[(k << 6) + (tx << 2)]);
        float4 a0 = *reinterpret_cast<const float4*>(&xsT[(k << 7) + (ty << 3)]);
        float4 a1 = *reinterpret_cast<const float4*>(&xsT[(k << 7) + (ty << 3) + 4]);
        float av[8] = {a0.x, a0.y, a0.z, a0.w, a1.x, a1.y, a1.z, a1.w};
        float bAv[4] = {bA.x, bA.y, bA.z, bA.w};
        float bBv[4] = {bB.x, bB.y, bB.z, bB.w};
        #pragma unroll
        for (int i = 0; i < 8; ++i) {
            float a  = av[i];
            float a2 = a * a;
            #pragma unroll
            for (int j = 0; j < 4; ++j) {
                accA[i][j] = fmaf(a2, bAv[j], accA[i][j]);
                accB[i][j] = fmaf(a,  bBv[j], accB[i][j]);
            }
        }
    }

    #pragma unroll
    for (int i = 0; i < 8; ++i) {
        int r = rowBase + ty * 8 + i;
        #pragma unroll
        for (int j = 0; j < 4; ++j) {
            int f = fBase + tx * 4 + j;
            float v = accA[i][j] - 2.f * accB[i][j] + __ldg(&g_c[f]);
            v = fmaxf(v, 0.f);
            g_loc[(size_t)r * NFORM + f] = expf(-sqrtf(v));
        }
    }
}

// ---------------------------------------------------------------------------
// K3: per-row softmax(sigmoid(T)*loc) and final multiply -> out
//   one warp per row; 256 threads -> 8 rows per CTA, grid = 512
// ---------------------------------------------------------------------------
__global__ __launch_bounds__(256) void k3_softmax(const float* __restrict__ temp,
                                                  float* __restrict__ out) {
    const int row  = blockIdx.x * 8 + (threadIdx.x >> 5);
    const int lane = threadIdx.x & 31;
    const float s = 1.f / (1.f + expf(-temp[0]));
    const size_t base = (size_t)row * NFORM;

    float z[8];
    float m = -1e30f;
    #pragma unroll
    for (int i = 0; i < 8; ++i) {
        z[i] = s * g_loc[base + lane + (i << 5)];
        m = fmaxf(m, z[i]);
    }
    #pragma unroll
    for (int off = 16; off > 0; off >>= 1)
        m = fmaxf(m, __shfl_xor_sync(0xFFFFFFFFu, m, off));
    float e[8];
    float sum = 0.f;
    #pragma unroll
    for (int i = 0; i < 8; ++i) { e[i] = expf(z[i] - m); sum += e[i]; }
    #pragma unroll
    for (int off = 16; off > 0; off >>= 1)
        sum += __shfl_xor_sync(0xFFFFFFFFu, sum, off);
    const float inv = 1.f / sum;
    #pragma unroll
    for (int i = 0; i < 8; ++i) {
        size_t idx = base + lane + (i << 5);
        out[idx] = g_dnnf[idx] * e[i] * inv;
    }
}

// ---------------------------------------------------------------------------
extern "C" void kernel_launch(void* const* d_in, const int* in_sizes, int n_in,
                              void* d_out, int out_size) {
    const float* x     = (const float*)d_in[0];
    const float* w     = (const float*)d_in[1];
    const float* bias  = (const float*)d_in[2];
    const float* lm    = (const float*)d_in[3];
    const float* mu    = (const float*)d_in[4];
    const float* sigma = (const float*)d_in[5];
    const float* temp  = (const float*)d_in[6];
    // d_in[7..9]: index arrays — structure is compile-time known, unused.
    float* out = (float*)d_out;

    cudaFuncSetAttribute(k1_literals, cudaFuncAttributeMaxDynamicSharedMemorySize, K1_SMEM_BYTES);
    cudaFuncSetAttribute(k2_loc,      cudaFuncAttributeMaxDynamicSharedMemorySize, K2_SMEM_BYTES);

    k0_precompute<<<NFORM, DIM>>>(mu, sigma);
    k1_literals<<<dim3(BATCH / K1_M, K1_TILES), 256, K1_SMEM_BYTES>>>(x, w, bias, lm);
    k2_loc<<<dim3(BATCH / K2_M, NFORM / K2_N), 256, K2_SMEM_BYTES>>>(x);
    k3_softmax<<<BATCH / 8, 256>>>(temp, out);
}

// round 2
// speedup vs baseline: 1.6626x; 1.6626x over previous
#include <cuda_runtime.h>
#include <cuda_bf16.h>
#include <math.h>

// ---------------------------------------------------------------------------
// Problem constants (structure fully deterministic from reference code)
// ---------------------------------------------------------------------------
#define BATCH      4096
#define DIM        128
#define NFORM      256
#define NLIT       10752
#define NCONJ      2688

#define K1_M       128
#define K1_N       64
#define K1_TILES   224
#define K2_M       128
#define K2_N       64

// Fast hardware tanh (sm_75+): single MUFU-class op, max rel err ~2^-11.
__device__ __forceinline__ float ftanh(float v) {
    float r;
    asm("tanh.approx.f32 %0, %1;" : "=f"(r) : "f"(v));
    return r;
}

// Scratch (device globals: no allocation allowed)
__device__ float g_dnnf[BATCH * NFORM];
__device__ float g_loc [BATCH * NFORM];
__device__ float g_A   [DIM * NFORM];
__device__ float g_Bv  [DIM * NFORM];
__device__ float g_c   [NFORM];

// ---------------------------------------------------------------------------
// K0: precompute sigma^2, mu*sigma^2, c[f]
// ---------------------------------------------------------------------------
__global__ void k0_precompute(const float* __restrict__ mu,
                              const float* __restrict__ sigma) {
    int f = blockIdx.x;
    int k = threadIdx.x;
    float sg = sigma[f * DIM + k];
    float m  = mu[f * DIM + k];
    float s2 = sg * sg;
    float bv = m * s2;
    g_A [k * NFORM + f] = s2;
    g_Bv[k * NFORM + f] = bv;
    float cp = m * bv;
    #pragma unroll
    for (int off = 16; off > 0; off >>= 1)
        cp += __shfl_xor_sync(0xFFFFFFFFu, cp, off);
    __shared__ float red[4];
    if ((k & 31) == 0) red[k >> 5] = cp;
    __syncthreads();
    if (k == 0) g_c[f] = red[0] + red[1] + red[2] + red[3];
}

// ---------------------------------------------------------------------------
// K1: fused literal GEMM + tanh + conjunction/formula reduction -> g_dnnf
// ---------------------------------------------------------------------------
#define K1_SMEM_FLOATS (DIM * K1_M + DIM * K1_N + K1_N)
#define K1_SMEM_BYTES  (K1_SMEM_FLOATS * 4)

__global__ __launch_bounds__(256) void k1_literals(
    const float* __restrict__ x, const float* __restrict__ w,
    const float* __restrict__ bias, const float* __restrict__ lm) {

    extern __shared__ __align__(16) float smem[];
    float* xsT = smem;                       // 128*128, k-major
    float* ws  = smem + DIM * K1_M;          // 128*64
    float* bs  = ws + DIM * K1_N;            // 64

    const int tile    = blockIdx.y;
    const int rowBase = blockIdx.x * K1_M;
    const int tid     = threadIdx.x;

    int g, f0, Lf, litBase, nFt;
    if (tile < 32)        { g = 0; f0 =       2 * tile;       Lf = 24; litBase =        48 * tile;        nFt = 2; }
    else if (tile < 96)   { g = 1; f0 =  64 + (tile - 32);    Lf = 36; litBase = 1536 + 36 * (tile - 32); nFt = 1; }
    else if (tile < 160)  { g = 2; f0 = 128 + (tile - 96);    Lf = 48; litBase = 3840 + 48 * (tile - 96); nFt = 1; }
    else                  { g = 3; f0 = 192 + (tile - 160);   Lf = 60; litBase = 6912 + 60 * (tile - 160);nFt = 1; }
    const int nlit = Lf * nFt;

    for (int e = tid; e < K1_M * (DIM / 4); e += 256) {
        int r  = e >> 5;
        int k4 = e & 31;
        float4 v = reinterpret_cast<const float4*>(x + (size_t)(rowBase + r) * DIM)[k4];
        xsT[(k4 * 4 + 0) * K1_M + r] = v.x;
        xsT[(k4 * 4 + 1) * K1_M + r] = v.y;
        xsT[(k4 * 4 + 2) * K1_M + r] = v.z;
        xsT[(k4 * 4 + 3) * K1_M + r] = v.w;
    }
    for (int e = tid; e < DIM * K1_N; e += 256) {
        int k = e >> 6;
        int j = e & 63;
        float wv = 0.f;
        if (j < nlit) {
            int f = f0 + ((j >= Lf) ? 1 : 0);
            float mk = (fabsf(lm[k * NFORM + f]) > 1.0f) ? 1.0f : 0.0f;
            wv = w[(size_t)k * NLIT + litBase + j] * mk;
        }
        ws[e] = wv;
    }
    if (tid < K1_N) bs[tid] = (tid < nlit) ? bias[litBase + tid] : 0.f;
    __syncthreads();

    const int tx = tid & 15;
    const int ty = tid >> 4;
    float acc[8][4];
    #pragma unroll
    for (int i = 0; i < 8; ++i)
        #pragma unroll
        for (int j = 0; j < 4; ++j) acc[i][j] = 0.f;

    #pragma unroll 8
    for (int k = 0; k < DIM; ++k) {
        float4 b4 = *reinterpret_cast<const float4*>(&ws[(k << 6) + (tx << 2)]);
        float4 a0 = *reinterpret_cast<const float4*>(&xsT[(k << 7) + (ty << 3)]);
        float4 a1 = *reinterpret_cast<const float4*>(&xsT[(k << 7) + (ty << 3) + 4]);
        float av[8] = {a0.x, a0.y, a0.z, a0.w, a1.x, a1.y, a1.z, a1.w};
        float bv[4] = {b4.x, b4.y, b4.z, b4.w};
        #pragma unroll
        for (int i = 0; i < 8; ++i)
            #pragma unroll
            for (int j = 0; j < 4; ++j)
                acc[i][j] = fmaf(av[i], bv[j], acc[i][j]);
    }
    __syncthreads();

    // tanh literals -> ct (reuse xsT region, stride 65 to dodge bank conflicts)
    float* ct = xsT;
    #pragma unroll
    for (int i = 0; i < 8; ++i) {
        int r = ty * 8 + i;
        #pragma unroll
        for (int j = 0; j < 4; ++j) {
            int c = tx * 4 + j;
            ct[r * 65 + c] = ftanh(acc[i][j] + bs[c]);
        }
    }
    __syncthreads();

    const int nd = 2 + g;
    const float ncf = (float)(6 + 3 * g);
    const int nTasks = K1_M * nFt;
    for (int task = tid; task < nTasks; task += 256) {
        int fi  = task >> 7;
        int row = task & 127;
        int off = fi * Lf;
        const float* cr = &ct[row * 65];
        float fs = 0.f;
        #pragma unroll
        for (int d = 2; d <= 6; d += 2) {
            for (int c = 0; c < nd; ++c) {
                float s = 0.f;
                #pragma unroll 6
                for (int u = 0; u < d; ++u) s += cr[off + u];
                fs += ftanh(s - (float)d + 1.5f);
                off += d;
            }
        }
        g_dnnf[(size_t)(rowBase + row) * NFORM + f0 + fi] = ftanh(fs + ncf - 1.5f);
    }
}

// ---------------------------------------------------------------------------
// K2: loc GEMM -> g_loc = exp(-||(x-mu)*sigma||)
// ---------------------------------------------------------------------------
#define K2_SMEM_FLOATS (DIM * K2_M + 2 * DIM * K2_N)
#define K2_SMEM_BYTES  (K2_SMEM_FLOATS * 4)

__global__ __launch_bounds__(256) void k2_loc(const float* __restrict__ x) {
    extern __shared__ __align__(16) float smem[];
    float* xsT = smem;
    float* At  = smem + DIM * K2_M;
    float* Bt  = At + DIM * K2_N;

    const int rowBase = blockIdx.x * K2_M;
    const int fBase   = blockIdx.y * K2_N;
    const int tid     = threadIdx.x;

    for (int e = tid; e < K2_M * (DIM / 4); e += 256) {
        int r  = e >> 5;
        int k4 = e & 31;
        float4 v = reinterpret_cast<const float4*>(x + (size_t)(rowBase + r) * DIM)[k4];
        xsT[(k4 * 4 + 0) * K2_M + r] = v.x;
        xsT[(k4 * 4 + 1) * K2_M + r] = v.y;
        xsT[(k4 * 4 + 2) * K2_M + r] = v.z;
        xsT[(k4 * 4 + 3) * K2_M + r] = v.w;
    }
    for (int e = tid; e < DIM * K2_N; e += 256) {
        int k = e >> 6;
        int j = e & 63;
        At[e] = g_A [k * NFORM + fBase + j];
        Bt[e] = g_Bv[k * NFORM + fBase + j];
    }
    __syncthreads();

    const int tx = tid & 15;
    const int ty = tid >> 4;
    float accA[8][4], accB[8][4];
    #pragma unroll
    for (int i = 0; i < 8; ++i)
        #pragma unroll
        for (int j = 0; j < 4; ++j) { accA[i][j] = 0.f; accB[i][j] = 0.f; }

    #pragma unroll 4
    for (int k = 0; k < DIM; ++k) {
        float4 bA = *reinterpret_cast<const float4*>(&At[(k << 6) + (tx << 2)]);
        float4 bB = *reinterpret_cast<const float4*>(&Bt[(k << 6) + (tx << 2)]);
        float4 a0 = *reinterpret_cast<const float4*>(&xsT[(k << 7) + (ty << 3)]);
        float4 a1 = *reinterpret_cast<const float4*>(&xsT[(k << 7) + (ty << 3) + 4]);
        float av[8] = {a0.x, a0.y, a0.z, a0.w, a1.x, a1.y, a1.z, a1.w};
        float bAv[4] = {bA.x, bA.y, bA.z, bA.w};
        float bBv[4] = {bB.x, bB.y, bB.z, bB.w};
        #pragma unroll
        for (int i = 0; i < 8; ++i) {
            float a  = av[i];
            float a2 = a * a;
            #pragma unroll
            for (int j = 0; j < 4; ++j) {
                accA[i][j] = fmaf(a2, bAv[j], accA[i][j]);
                accB[i][j] = fmaf(a,  bBv[j], accB[i][j]);
            }
        }
    }

    #pragma unroll
    for (int i = 0; i < 8; ++i) {
        int r = rowBase + ty * 8 + i;
        #pragma unroll
        for (int j = 0; j < 4; ++j) {
            int f = fBase + tx * 4 + j;
            float v = accA[i][j] - 2.f * accB[i][j] + __ldg(&g_c[f]);
            v = fmaxf(v, 0.f);
            g_loc[(size_t)r * NFORM + f] = __expf(-__fsqrt_rn(v));
        }
    }
}

// ---------------------------------------------------------------------------
// K3: per-row softmax(sigmoid(T)*loc) * dnnf -> out
// ---------------------------------------------------------------------------
__global__ __launch_bounds__(256) void k3_softmax(const float* __restrict__ temp,
                                                  float* __restrict__ out) {
    const int row  = blockIdx.x * 8 + (threadIdx.x >> 5);
    const int lane = threadIdx.x & 31;
    const float s = 1.f / (1.f + __expf(-temp[0]));
    const size_t base = (size_t)row * NFORM;

    float z[8];
    float m = -1e30f;
    #pragma unroll
    for (int i = 0; i < 8; ++i) {
        z[i] = s * g_loc[base + lane + (i << 5)];
        m = fmaxf(m, z[i]);
    }
    #pragma unroll
    for (int off = 16; off > 0; off >>= 1)
        m = fmaxf(m, __shfl_xor_sync(0xFFFFFFFFu, m, off));
    float e[8];
    float sum = 0.f;
    #pragma unroll
    for (int i = 0; i < 8; ++i) { e[i] = __expf(z[i] - m); sum += e[i]; }
    #pragma unroll
    for (int off = 16; off > 0; off >>= 1)
        sum += __shfl_xor_sync(0xFFFFFFFFu, sum, off);
    const float inv = 1.f / sum;
    #pragma unroll
    for (int i = 0; i < 8; ++i) {
        size_t idx = base + lane + (i << 5);
        out[idx] = g_dnnf[idx] * e[i] * inv;
    }
}

// ---------------------------------------------------------------------------
extern "C" void kernel_launch(void* const* d_in, const int* in_sizes, int n_in,
                              void* d_out, int out_size) {
    const float* x     = (const float*)d_in[0];
    const float* w     = (const float*)d_in[1];
    const float* bias  = (const float*)d_in[2];
    const float* lm    = (const float*)d_in[3];
    const float* mu    = (const float*)d_in[4];
    const float* sigma = (const float*)d_in[5];
    const float* temp  = (const float*)d_in[6];
    float* out = (float*)d_out;

    cudaFuncSetAttribute(k1_literals, cudaFuncAttributeMaxDynamicSharedMemorySize, K1_SMEM_BYTES);
    cudaFuncSetAttribute(k2_loc,      cudaFuncAttributeMaxDynamicSharedMemorySize, K2_SMEM_BYTES);

    k0_precompute<<<NFORM, DIM>>>(mu, sigma);
    k1_literals<<<dim3(BATCH / K1_M, K1_TILES), 256, K1_SMEM_BYTES>>>(x, w, bias, lm);
    k2_loc<<<dim3(BATCH / K2_M, NFORM / K2_N), 256, K2_SMEM_BYTES>>>(x);
    k3_softmax<<<BATCH / 8, 256>>>(temp, out);
}

// round 4
// speedup vs baseline: 4.8688x; 2.9283x over previous
#include <cuda_runtime.h>
#include <cuda_bf16.h>
#include <math.h>
#include <stdint.h>

// ---------------------------------------------------------------------------
// Problem constants
// ---------------------------------------------------------------------------
#define BATCH      4096
#define DIM        128
#define NFORM      256
#define NLIT       10752

#define K2_M       128
#define K2_N       64

// ---------------------------------------------------------------------------
// Helpers (portable PTX only: ldmatrix + mma.sync, legal at compute_103)
// ---------------------------------------------------------------------------
__device__ __forceinline__ float ftanh(float v) {
    float r; asm("tanh.approx.f32 %0, %1;" : "=f"(r) : "f"(v)); return r;
}
__device__ __forceinline__ uint32_t smem_u32(const void* p) {
    uint32_t a;
    asm("{ .reg .u64 t; cvta.to.shared.u64 t, %1; cvt.u32.u64 %0, t; }" : "=r"(a) : "l"(p));
    return a;
}
__device__ __forceinline__ void ldsm_x4(uint32_t& r0, uint32_t& r1, uint32_t& r2, uint32_t& r3,
                                        uint32_t addr) {
    asm volatile("ldmatrix.sync.aligned.m8n8.x4.shared.b16 {%0,%1,%2,%3}, [%4];"
                 : "=r"(r0), "=r"(r1), "=r"(r2), "=r"(r3) : "r"(addr));
}
__device__ __forceinline__ void ldsm_x2(uint32_t& r0, uint32_t& r1, uint32_t addr) {
    asm volatile("ldmatrix.sync.aligned.m8n8.x2.shared.b16 {%0,%1}, [%2];"
                 : "=r"(r0), "=r"(r1) : "r"(addr));
}
__device__ __forceinline__ void mma16816(float* c, uint32_t a0, uint32_t a1, uint32_t a2,
                                         uint32_t a3, uint32_t b0, uint32_t b1) {
    asm volatile("mma.sync.aligned.m16n8k16.row.col.f32.bf16.bf16.f32 "
                 "{%0,%1,%2,%3}, {%4,%5,%6,%7}, {%8,%9}, {%0,%1,%2,%3};"
                 : "+f"(c[0]), "+f"(c[1]), "+f"(c[2]), "+f"(c[3])
                 : "r"(a0), "r"(a1), "r"(a2), "r"(a3), "r"(b0), "r"(b1));
}

// ---------------------------------------------------------------------------
// Scratch (device globals)
// ---------------------------------------------------------------------------
__device__ float          g_dnnf[BATCH * NFORM];
__device__ float          g_loc [BATCH * NFORM];
__device__ float          g_A   [DIM * NFORM];
__device__ float          g_Bv  [DIM * NFORM];
__device__ float          g_c   [NFORM];
__device__ __nv_bfloat16  g_x_hi[BATCH * DIM];
__device__ __nv_bfloat16  g_x_lo[BATCH * DIM];
__device__ __nv_bfloat16  g_wt_hi[(size_t)NLIT * DIM];   // [l][k], literal-major
__device__ __nv_bfloat16  g_wt_lo[(size_t)NLIT * DIM];

// ---------------------------------------------------------------------------
// K0a: sigma^2 / mu*sigma^2 / c   (for K2)
// ---------------------------------------------------------------------------
__global__ void k0_precompute(const float* __restrict__ mu,
                              const float* __restrict__ sigma) {
    int f = blockIdx.x, k = threadIdx.x;
    float sg = sigma[f * DIM + k];
    float m  = mu[f * DIM + k];
    float s2 = sg * sg;
    float bv = m * s2;
    g_A [k * NFORM + f] = s2;
    g_Bv[k * NFORM + f] = bv;
    float cp = m * bv;
    #pragma unroll
    for (int off = 16; off > 0; off >>= 1)
        cp += __shfl_xor_sync(0xFFFFFFFFu, cp, off);
    __shared__ float red[4];
    if ((k & 31) == 0) red[k >> 5] = cp;
    __syncthreads();
    if (k == 0) g_c[f] = red[0] + red[1] + red[2] + red[3];
}

// ---------------------------------------------------------------------------
// K0b: split x into bf16 hi/lo
// ---------------------------------------------------------------------------
__device__ __forceinline__ void split2(float v0, float v1, uint32_t& hi, uint32_t& lo) {
    __nv_bfloat16 h0 = __float2bfloat16(v0), h1 = __float2bfloat16(v1);
    __nv_bfloat16 l0 = __float2bfloat16(v0 - __bfloat162float(h0));
    __nv_bfloat16 l1 = __float2bfloat16(v1 - __bfloat162float(h1));
    __nv_bfloat162 hh = __halves2bfloat162(h0, h1);
    __nv_bfloat162 ll = __halves2bfloat162(l0, l1);
    hi = *reinterpret_cast<uint32_t*>(&hh);
    lo = *reinterpret_cast<uint32_t*>(&ll);
}

__global__ __launch_bounds__(256) void k0_split_x(const float* __restrict__ x) {
    int e = blockIdx.x * 256 + threadIdx.x;
    const float4* src = reinterpret_cast<const float4*>(x) + (size_t)e * 2;
    float4 a = src[0], b = src[1];
    float v[8] = {a.x, a.y, a.z, a.w, b.x, b.y, b.z, b.w};
    uint32_t hi[4], lo[4];
    #pragma unroll
    for (int p = 0; p < 4; ++p) split2(v[2*p], v[2*p+1], hi[p], lo[p]);
    reinterpret_cast<uint4*>(g_x_hi)[e] = make_uint4(hi[0], hi[1], hi[2], hi[3]);
    reinterpret_cast<uint4*>(g_x_lo)[e] = make_uint4(lo[0], lo[1], lo[2], lo[3]);
}

// ---------------------------------------------------------------------------
// K0c: masked W -> transposed (literal-major) bf16 hi/lo
// ---------------------------------------------------------------------------
__global__ __launch_bounds__(256) void k0_split_w(const float* __restrict__ w,
                                                  const float* __restrict__ lm) {
    __shared__ float s[128 * 65];
    const int l0  = blockIdx.x * 64;
    const int tid = threadIdx.x;
    for (int e = tid; e < 128 * 64; e += 256) {
        int k = e >> 6, j = e & 63;
        int l = l0 + j;
        int f;
        if      (l < 1536) f = l / 24;
        else if (l < 3840) f = 64  + (l - 1536) / 36;
        else if (l < 6912) f = 128 + (l - 3840) / 48;
        else               f = 192 + (l - 6912) / 60;
        float mk = (fabsf(lm[k * NFORM + f]) > 1.0f) ? 1.0f : 0.0f;
        s[k * 65 + j] = w[(size_t)k * NLIT + l] * mk;
    }
    __syncthreads();
    for (int e = tid; e < 64 * 16; e += 256) {
        int row = e >> 4, chunk = e & 15;
        uint32_t hi[4], lo[4];
        #pragma unroll
        for (int p = 0; p < 4; ++p)
            split2(s[(chunk * 8 + 2*p) * 65 + row], s[(chunk * 8 + 2*p + 1) * 65 + row],
                   hi[p], lo[p]);
        size_t l = l0 + row;
        reinterpret_cast<uint4*>(g_wt_hi + l * DIM)[chunk] = make_uint4(hi[0], hi[1], hi[2], hi[3]);
        reinterpret_cast<uint4*>(g_wt_lo + l * DIM)[chunk] = make_uint4(lo[0], lo[1], lo[2], lo[3]);
    }
}

// ---------------------------------------------------------------------------
// K1: HMMA (mma.sync bf16) literal GEMM + fused tanh/segmented reduce
//   CTA: M=128 rows x N=128 cols (two formula-aligned 64-blocks), K=128.
//   8 warps, warp = 16 rows x 128 cols. 3 bf16-split passes, A refilled.
// ---------------------------------------------------------------------------
#define RSTRIDE   272                       // bytes per smem row (136 bf16)
#define SM_BIAS   0                         // 128 floats
#define SM_A      1024                      // 128*272 = 34816
#define SM_BH     (SM_A + 34816)            // 35840
#define SM_BL     (SM_BH + 34816)           // 70656
#define K1_SMEM   (SM_BL + 34816)           // 105472

template<int G>
__global__ __launch_bounds__(256, 2) void k1_tensor(const float* __restrict__ bias) {
    constexpr int LF    = 24 + 12 * G;         // literals per formula
    constexpr int NFT   = (G == 0) ? 2 : 1;    // formulas per 64-block
    constexpr int ND    = 2 + G;               // conjs per depth
    constexpr int BLIT  = LF * NFT;            // live literals per 64-block
    constexpr int F0B   = 64 * G;
    constexpr int LB0   = (G == 0) ? 0 : (G == 1 ? 1536 : (G == 2 ? 3840 : 6912));
    constexpr int NF    = 2 * NFT;             // formulas per CTA

    extern __shared__ __align__(1024) char smem[];
    const uint32_t sb = smem_u32(smem);
    float* bs = reinterpret_cast<float*>(smem + SM_BIAS);

    const int tid     = threadIdx.x;
    const int wid     = tid >> 5;
    const int lane    = tid & 31;
    const int rowBase = blockIdx.x * 128;
    const int ty      = blockIdx.y;
    const int f0g     = F0B + 2 * ty * NFT;
    const int lb[2]   = { LB0 + (2 * ty)     * BLIT,
                          LB0 + (2 * ty + 1) * BLIT };

    // ---- bias ----
    if (tid < 128) {
        int s = tid >> 6, j = tid & 63;
        bs[tid] = (j < BLIT) ? bias[lb[s] + j] : 0.f;
    }
    // ---- B fill (both splits): 2 x 128 rows x 16 uint4 ----
    for (int e = tid; e < 4096; e += 256) {
        int buf = e >> 11;                   // 0 = hi, 1 = lo
        int n   = (e >> 4) & 127;
        int ch  = e & 15;
        int s = n >> 6, j = n & 63;
        uint4 v = make_uint4(0, 0, 0, 0);
        if (j < BLIT) {
            const __nv_bfloat16* wt = buf ? g_wt_lo : g_wt_hi;
            v = reinterpret_cast<const uint4*>(wt + (size_t)(lb[s] + j) * DIM)[ch];
        }
        *reinterpret_cast<uint4*>(smem + (buf ? SM_BL : SM_BH) + n * RSTRIDE + ch * 16) = v;
    }
    // ---- A fill (hi) ----
    for (int e = tid; e < 2048; e += 256) {
        int r = e >> 4, ch = e & 15;
        *reinterpret_cast<uint4*>(smem + SM_A + r * RSTRIDE + ch * 16) =
            reinterpret_cast<const uint4*>(g_x_hi + (size_t)(rowBase + r) * DIM)[ch];
    }
    __syncthreads();

    // per-thread ldmatrix source offsets
    const uint32_t aoff = sb + SM_A +
        (uint32_t)((16 * wid + (lane & 7) + ((lane >> 3) & 1) * 8) * RSTRIDE + (lane >> 4) * 16);
    const uint32_t boff = (uint32_t)((lane & 7) * RSTRIDE + ((lane >> 3) & 1) * 16);

    float acc[16][4];
    #pragma unroll
    for (int nt = 0; nt < 16; ++nt)
        #pragma unroll
        for (int j = 0; j < 4; ++j) acc[nt][j] = 0.f;

    // pass 0: A_hi x B_hi ; pass 1: A_hi x B_lo
    #pragma unroll
    for (int p = 0; p < 2; ++p) {
        const uint32_t bbase = sb + (p ? SM_BL : SM_BH) + boff;
        #pragma unroll
        for (int kk = 0; kk < 8; ++kk) {
            uint32_t a0, a1, a2, a3;
            ldsm_x4(a0, a1, a2, a3, aoff + kk * 32);
            #pragma unroll
            for (int nt = 0; nt < 16; ++nt) {
                uint32_t b0, b1;
                ldsm_x2(b0, b1, bbase + nt * (8 * RSTRIDE) + kk * 32);
                mma16816(acc[nt], a0, a1, a2, a3, b0, b1);
            }
        }
    }
    __syncthreads();
    // refill A with lo split
    for (int e = tid; e < 2048; e += 256) {
        int r = e >> 4, ch = e & 15;
        *reinterpret_cast<uint4*>(smem + SM_A + r * RSTRIDE + ch * 16) =
            reinterpret_cast<const uint4*>(g_x_lo + (size_t)(rowBase + r) * DIM)[ch];
    }
    __syncthreads();
    // pass 2: A_lo x B_hi
    {
        const uint32_t bbase = sb + SM_BH + boff;
        #pragma unroll
        for (int kk = 0; kk < 8; ++kk) {
            uint32_t a0, a1, a2, a3;
            ldsm_x4(a0, a1, a2, a3, aoff + kk * 32);
            #pragma unroll
            for (int nt = 0; nt < 16; ++nt) {
                uint32_t b0, b1;
                ldsm_x2(b0, b1, bbase + nt * (8 * RSTRIDE) + kk * 32);
                mma16816(acc[nt], a0, a1, a2, a3, b0, b1);
            }
        }
    }
    __syncthreads();   // all warps done reading A/B smem

    // ---- tanh(literal) -> ct[128][129] (overlaps A+BH regions) ----
    float* ct = reinterpret_cast<float*>(smem + SM_A);
    {
        const int gidr = lane >> 2;          // 0..7
        const int tig  = lane & 3;           // 0..3
        const int r0 = 16 * wid + gidr;
        #pragma unroll
        for (int nt = 0; nt < 16; ++nt) {
            const int c0 = nt * 8 + 2 * tig;
            ct[r0 * 129 + c0]           = ftanh(acc[nt][0] + bs[c0]);
            ct[r0 * 129 + c0 + 1]       = ftanh(acc[nt][1] + bs[c0 + 1]);
            ct[(r0 + 8) * 129 + c0]     = ftanh(acc[nt][2] + bs[c0]);
            ct[(r0 + 8) * 129 + c0 + 1] = ftanh(acc[nt][3] + bs[c0 + 1]);
        }
    }
    __syncthreads();

    // ---- segmented reduce: conj (depths 2/4/6, ND each) -> formula ----
    for (int task = tid; task < 128 * NF; task += 256) {
        const int row = task & 127;
        const int fi  = task >> 7;
        const int cb  = (G == 0) ? ((fi >> 1) * 64 + (fi & 1) * LF) : (fi * 64);
        const float* cr = &ct[row * 129 + cb];
        float fs = 0.f;
        int off = 0;
        #pragma unroll
        for (int dd = 0; dd < 3; ++dd) {
            const int d = 2 + 2 * dd;
            #pragma unroll
            for (int c = 0; c < ND; ++c) {
                float s = 0.f;
                #pragma unroll
                for (int u = 0; u < 6; ++u)
                    if (u < d) s += cr[off + u];
                fs += ftanh(s - (float)d + 1.5f);
                off += d;
            }
        }
        g_dnnf[(size_t)(rowBase + row) * NFORM + f0g + fi] = ftanh(fs + (float)(3 * ND) - 1.5f);
    }
}

// ---------------------------------------------------------------------------
// K2: loc GEMM (SIMT fp32) -> g_loc = exp(-||(x-mu)*sigma||)
// ---------------------------------------------------------------------------
#define K2_SMEM_BYTES ((DIM * K2_M + 2 * DIM * K2_N) * 4)

__global__ __launch_bounds__(256) void k2_loc(const float* __restrict__ x) {
    extern __shared__ __align__(16) float sm2[];
    float* xsT = sm2;
    float* At  = sm2 + DIM * K2_M;
    float* Bt  = At + DIM * K2_N;

    const int rowBase = blockIdx.x * K2_M;
    const int fBase   = blockIdx.y * K2_N;
    const int tid     = threadIdx.x;

    for (int e = tid; e < K2_M * (DIM / 4); e += 256) {
        int r = e >> 5, k4 = e & 31;
        float4 v = reinterpret_cast<const float4*>(x + (size_t)(rowBase + r) * DIM)[k4];
        xsT[(k4 * 4 + 0) * K2_M + r] = v.x;
        xsT[(k4 * 4 + 1) * K2_M + r] = v.y;
        xsT[(k4 * 4 + 2) * K2_M + r] = v.z;
        xsT[(k4 * 4 + 3) * K2_M + r] = v.w;
    }
    for (int e = tid; e < DIM * K2_N; e += 256) {
        int k = e >> 6, j = e & 63;
        At[e] = g_A [k * NFORM + fBase + j];
        Bt[e] = g_Bv[k * NFORM + fBase + j];
    }
    __syncthreads();

    const int tx = tid & 15, ty = tid >> 4;
    float accA[8][4], accB[8][4];
    #pragma unroll
    for (int i = 0; i < 8; ++i)
        #pragma unroll
        for (int j = 0; j < 4; ++j) { accA[i][j] = 0.f; accB[i][j] = 0.f; }

    #pragma unroll 4
    for (int k = 0; k < DIM; ++k) {
        float4 bA = *reinterpret_cast<const float4*>(&At[(k << 6) + (tx << 2)]);
        float4 bB = *reinterpret_cast<const float4*>(&Bt[(k << 6) + (tx << 2)]);
        float4 a0 = *reinterpret_cast<const float4*>(&xsT[(k << 7) + (ty << 3)]);
        float4 a1 = *reinterpret_cast<const float4*>(&xsT[(k << 7) + (ty << 3) + 4]);
        float av[8] = {a0.x, a0.y, a0.z, a0.w, a1.x, a1.y, a1.z, a1.w};
        float bAv[4] = {bA.x, bA.y, bA.z, bA.w};
        float bBv[4] = {bB.x, bB.y, bB.z, bB.w};
        #pragma unroll
        for (int i = 0; i < 8; ++i) {
            float a = av[i], a2 = a * a;
            #pragma unroll
            for (int j = 0; j < 4; ++j) {
                accA[i][j] = fmaf(a2, bAv[j], accA[i][j]);
                accB[i][j] = fmaf(a,  bBv[j], accB[i][j]);
            }
        }
    }

    #pragma unroll
    for (int i = 0; i < 8; ++i) {
        int r = rowBase + ty * 8 + i;
        #pragma unroll
        for (int j = 0; j < 4; ++j) {
            int f = fBase + tx * 4 + j;
            float v = accA[i][j] - 2.f * accB[i][j] + __ldg(&g_c[f]);
            v = fmaxf(v, 0.f);
            g_loc[(size_t)r * NFORM + f] = __expf(-__fsqrt_rn(v));
        }
    }
}

// ---------------------------------------------------------------------------
// K3: per-row softmax(sigmoid(T)*loc) * dnnf -> out
// ---------------------------------------------------------------------------
__global__ __launch_bounds__(256) void k3_softmax(const float* __restrict__ temp,
                                                  float* __restrict__ out) {
    const int row  = blockIdx.x * 8 + (threadIdx.x >> 5);
    const int lane = threadIdx.x & 31;
    const float s = 1.f / (1.f + __expf(-temp[0]));
    const size_t base = (size_t)row * NFORM;

    float z[8];
    float m = -1e30f;
    #pragma unroll
    for (int i = 0; i < 8; ++i) {
        z[i] = s * g_loc[base + lane + (i << 5)];
        m = fmaxf(m, z[i]);
    }
    #pragma unroll
    for (int off = 16; off > 0; off >>= 1)
        m = fmaxf(m, __shfl_xor_sync(0xFFFFFFFFu, m, off));
    float e[8], sum = 0.f;
    #pragma unroll
    for (int i = 0; i < 8; ++i) { e[i] = __expf(z[i] - m); sum += e[i]; }
    #pragma unroll
    for (int off = 16; off > 0; off >>= 1)
        sum += __shfl_xor_sync(0xFFFFFFFFu, sum, off);
    const float inv = 1.f / sum;
    #pragma unroll
    for (int i = 0; i < 8; ++i) {
        size_t idx = base + lane + (i << 5);
        out[idx] = g_dnnf[idx] * e[i] * inv;
    }
}

// ---------------------------------------------------------------------------
extern "C" void kernel_launch(void* const* d_in, const int* in_sizes, int n_in,
                              void* d_out, int out_size) {
    const float* x     = (const float*)d_in[0];
    const float* w     = (const float*)d_in[1];
    const float* bias  = (const float*)d_in[2];
    const float* lm    = (const float*)d_in[3];
    const float* mu    = (const float*)d_in[4];
    const float* sigma = (const float*)d_in[5];
    const float* temp  = (const float*)d_in[6];
    float* out = (float*)d_out;

    cudaFuncSetAttribute(k1_tensor<0>, cudaFuncAttributeMaxDynamicSharedMemorySize, K1_SMEM);
    cudaFuncSetAttribute(k1_tensor<1>, cudaFuncAttributeMaxDynamicSharedMemorySize, K1_SMEM);
    cudaFuncSetAttribute(k1_tensor<2>, cudaFuncAttributeMaxDynamicSharedMemorySize, K1_SMEM);
    cudaFuncSetAttribute(k1_tensor<3>, cudaFuncAttributeMaxDynamicSharedMemorySize, K1_SMEM);
    cudaFuncSetAttribute(k2_loc,       cudaFuncAttributeMaxDynamicSharedMemorySize, K2_SMEM_BYTES);

    k0_precompute<<<NFORM, DIM>>>(mu, sigma);
    k0_split_x<<<BATCH * DIM / (256 * 8), 256>>>(x);
    k0_split_w<<<NLIT / 64, 256>>>(w, lm);
    // CTA covers two 64-blocks: G0 has 32 blocks -> 16 CTAs-y; G1..3: 64 -> 32
    k1_tensor<0><<<dim3(32, 16), 256, K1_SMEM>>>(bias);
    k1_tensor<1><<<dim3(32, 32), 256, K1_SMEM>>>(bias);
    k1_tensor<2><<<dim3(32, 32), 256, K1_SMEM>>>(bias);
    k1_tensor<3><<<dim3(32, 32), 256, K1_SMEM>>>(bias);
    k2_loc<<<dim3(BATCH / K2_M, NFORM / K2_N), 256, K2_SMEM_BYTES>>>(x);
    k3_softmax<<<BATCH / 8, 256>>>(temp, out);
}

// round 5
// speedup vs baseline: 5.0932x; 1.0461x over previous
#include <cuda_runtime.h>
#include <cuda_bf16.h>
#include <math.h>
#include <stdint.h>

// ---------------------------------------------------------------------------
// Problem constants
// ---------------------------------------------------------------------------
#define BATCH      4096
#define DIM        128
#define NFORM      256
#define NLIT       10752

#define K2_M       128
#define K2_N       64

// ---------------------------------------------------------------------------
// Helpers (portable PTX only: ldmatrix + mma.sync, legal at compute_103)
// ---------------------------------------------------------------------------
__device__ __forceinline__ float ftanh(float v) {
    float r; asm("tanh.approx.f32 %0, %1;" : "=f"(r) : "f"(v)); return r;
}
__device__ __forceinline__ uint32_t smem_u32(const void* p) {
    uint32_t a;
    asm("{ .reg .u64 t; cvta.to.shared.u64 t, %1; cvt.u32.u64 %0, t; }" : "=r"(a) : "l"(p));
    return a;
}
__device__ __forceinline__ void ldsm_x4(uint32_t& r0, uint32_t& r1, uint32_t& r2, uint32_t& r3,
                                        uint32_t addr) {
    asm volatile("ldmatrix.sync.aligned.m8n8.x4.shared.b16 {%0,%1,%2,%3}, [%4];"
                 : "=r"(r0), "=r"(r1), "=r"(r2), "=r"(r3) : "r"(addr));
}
__device__ __forceinline__ void mma16816(float* c, uint32_t a0, uint32_t a1, uint32_t a2,
                                         uint32_t a3, uint32_t b0, uint32_t b1) {
    asm volatile("mma.sync.aligned.m16n8k16.row.col.f32.bf16.bf16.f32 "
                 "{%0,%1,%2,%3}, {%4,%5,%6,%7}, {%8,%9}, {%0,%1,%2,%3};"
                 : "+f"(c[0]), "+f"(c[1]), "+f"(c[2]), "+f"(c[3])
                 : "r"(a0), "r"(a1), "r"(a2), "r"(a3), "r"(b0), "r"(b1));
}

// ---------------------------------------------------------------------------
// Scratch (device globals)
// ---------------------------------------------------------------------------
__device__ float          g_dnnf[BATCH * NFORM];
__device__ float          g_loc [BATCH * NFORM];
__device__ float          g_A   [DIM * NFORM];
__device__ float          g_Bv  [DIM * NFORM];
__device__ float          g_c   [NFORM];
__device__ __nv_bfloat16  g_x_hi[BATCH * DIM];
__device__ __nv_bfloat16  g_x_lo[BATCH * DIM];
__device__ __nv_bfloat16  g_wt_hi[(size_t)NLIT * DIM];   // [l][k], literal-major
__device__ __nv_bfloat16  g_wt_lo[(size_t)NLIT * DIM];

// ---------------------------------------------------------------------------
// K0a: sigma^2 / mu*sigma^2 / c   (for K2)
// ---------------------------------------------------------------------------
__global__ void k0_precompute(const float* __restrict__ mu,
                              const float* __restrict__ sigma) {
    int f = blockIdx.x, k = threadIdx.x;
    float sg = sigma[f * DIM + k];
    float m  = mu[f * DIM + k];
    float s2 = sg * sg;
    float bv = m * s2;
    g_A [k * NFORM + f] = s2;
    g_Bv[k * NFORM + f] = bv;
    float cp = m * bv;
    #pragma unroll
    for (int off = 16; off > 0; off >>= 1)
        cp += __shfl_xor_sync(0xFFFFFFFFu, cp, off);
    __shared__ float red[4];
    if ((k & 31) == 0) red[k >> 5] = cp;
    __syncthreads();
    if (k == 0) g_c[f] = red[0] + red[1] + red[2] + red[3];
}

// ---------------------------------------------------------------------------
// K0b: split x into bf16 hi/lo
// ---------------------------------------------------------------------------
__device__ __forceinline__ void split2(float v0, float v1, uint32_t& hi, uint32_t& lo) {
    __nv_bfloat16 h0 = __float2bfloat16(v0), h1 = __float2bfloat16(v1);
    __nv_bfloat16 l0 = __float2bfloat16(v0 - __bfloat162float(h0));
    __nv_bfloat16 l1 = __float2bfloat16(v1 - __bfloat162float(h1));
    __nv_bfloat162 hh = __halves2bfloat162(h0, h1);
    __nv_bfloat162 ll = __halves2bfloat162(l0, l1);
    hi = *reinterpret_cast<uint32_t*>(&hh);
    lo = *reinterpret_cast<uint32_t*>(&ll);
}

__global__ __launch_bounds__(256) void k0_split_x(const float* __restrict__ x) {
    int e = blockIdx.x * 256 + threadIdx.x;
    const float4* src = reinterpret_cast<const float4*>(x) + (size_t)e * 2;
    float4 a = src[0], b = src[1];
    float v[8] = {a.x, a.y, a.z, a.w, b.x, b.y, b.z, b.w};
    uint32_t hi[4], lo[4];
    #pragma unroll
    for (int p = 0; p < 4; ++p) split2(v[2*p], v[2*p+1], hi[p], lo[p]);
    reinterpret_cast<uint4*>(g_x_hi)[e] = make_uint4(hi[0], hi[1], hi[2], hi[3]);
    reinterpret_cast<uint4*>(g_x_lo)[e] = make_uint4(lo[0], lo[1], lo[2], lo[3]);
}

// ---------------------------------------------------------------------------
// K0c: masked W -> transposed (literal-major) bf16 hi/lo
// ---------------------------------------------------------------------------
__global__ __launch_bounds__(256) void k0_split_w(const float* __restrict__ w,
                                                  const float* __restrict__ lm) {
    __shared__ float s[128 * 65];
    const int l0  = blockIdx.x * 64;
    const int tid = threadIdx.x;
    for (int e = tid; e < 128 * 64; e += 256) {
        int k = e >> 6, j = e & 63;
        int l = l0 + j;
        int f;
        if      (l < 1536) f = l / 24;
        else if (l < 3840) f = 64  + (l - 1536) / 36;
        else if (l < 6912) f = 128 + (l - 3840) / 48;
        else               f = 192 + (l - 6912) / 60;
        float mk = (fabsf(lm[k * NFORM + f]) > 1.0f) ? 1.0f : 0.0f;
        s[k * 65 + j] = w[(size_t)k * NLIT + l] * mk;
    }
    __syncthreads();
    for (int e = tid; e < 64 * 16; e += 256) {
        int row = e >> 4, chunk = e & 15;
        uint32_t hi[4], lo[4];
        #pragma unroll
        for (int p = 0; p < 4; ++p)
            split2(s[(chunk * 8 + 2*p) * 65 + row], s[(chunk * 8 + 2*p + 1) * 65 + row],
                   hi[p], lo[p]);
        size_t l = l0 + row;
        reinterpret_cast<uint4*>(g_wt_hi + l * DIM)[chunk] = make_uint4(hi[0], hi[1], hi[2], hi[3]);
        reinterpret_cast<uint4*>(g_wt_lo + l * DIM)[chunk] = make_uint4(lo[0], lo[1], lo[2], lo[3]);
    }
}

// ---------------------------------------------------------------------------
// K1: HMMA (mma.sync bf16) literal GEMM + fused tanh/segmented reduce
//   CTA: M=128 x N=128 (two formula-aligned 64-blocks), K=128.
//   8 warps in 4(M) x 2(N): warp tile = M32 x N64. 3 bf16-split passes.
// ---------------------------------------------------------------------------
#define RSTRIDE   272                       // bytes per smem row (136 bf16)
#define SM_BIAS   0                         // 128 floats
#define SM_A      1024                      // 128*272 = 34816
#define SM_BH     (SM_A + 34816)            // 35840
#define SM_BL     (SM_BH + 34816)           // 70656
#define K1_SMEM   (SM_BL + 34816)           // 105472

template<int G>
__global__ __launch_bounds__(256, 2) void k1_tensor(const float* __restrict__ bias) {
    constexpr int LF    = 24 + 12 * G;
    constexpr int NFT   = (G == 0) ? 2 : 1;
    constexpr int ND    = 2 + G;
    constexpr int BLIT  = LF * NFT;
    constexpr int F0B   = 64 * G;
    constexpr int LB0   = (G == 0) ? 0 : (G == 1 ? 1536 : (G == 2 ? 3840 : 6912));
    constexpr int NF    = 2 * NFT;

    extern __shared__ __align__(1024) char smem[];
    const uint32_t sb = smem_u32(smem);
    float* bs = reinterpret_cast<float*>(smem + SM_BIAS);

    const int tid     = threadIdx.x;
    const int wid     = tid >> 5;
    const int lane    = tid & 31;
    const int rowBase = blockIdx.x * 128;
    const int ty      = blockIdx.y;
    const int f0g     = F0B + 2 * ty * NFT;
    const int lb[2]   = { LB0 + (2 * ty)     * BLIT,
                          LB0 + (2 * ty + 1) * BLIT };

    // ---- bias ----
    if (tid < 128) {
        int s = tid >> 6, j = tid & 63;
        bs[tid] = (j < BLIT) ? bias[lb[s] + j] : 0.f;
    }
    // ---- B fill (both splits) ----
    for (int e = tid; e < 4096; e += 256) {
        int buf = e >> 11;
        int n   = (e >> 4) & 127;
        int ch  = e & 15;
        int s = n >> 6, j = n & 63;
        uint4 v = make_uint4(0, 0, 0, 0);
        if (j < BLIT) {
            const __nv_bfloat16* wt = buf ? g_wt_lo : g_wt_hi;
            v = reinterpret_cast<const uint4*>(wt + (size_t)(lb[s] + j) * DIM)[ch];
        }
        *reinterpret_cast<uint4*>(smem + (buf ? SM_BL : SM_BH) + n * RSTRIDE + ch * 16) = v;
    }
    // ---- A fill (hi) ----
    for (int e = tid; e < 2048; e += 256) {
        int r = e >> 4, ch = e & 15;
        *reinterpret_cast<uint4*>(smem + SM_A + r * RSTRIDE + ch * 16) =
            reinterpret_cast<const uint4*>(g_x_hi + (size_t)(rowBase + r) * DIM)[ch];
    }
    __syncthreads();

    // warp grid 4(M) x 2(N): warp tile M32 x N64
    const int wm = wid & 3;                  // 0..3 -> row block of 32
    const int wn = wid >> 2;                 // 0..1 -> col block of 64
    const int mrow = wm * 32;
    const int ncol = wn * 64;

    // A ldmatrix base: rows mrow + (lane&15), 16B chunk = (lane>>4)
    const uint32_t aoff0 = sb + SM_A +
        (uint32_t)((mrow + (lane & 15)) * RSTRIDE + (lane >> 4) * 16);
    const uint32_t aoff1 = aoff0 + 16 * RSTRIDE;
    // B ldmatrix base (x4 = two n8 tiles): rows (lane&7) + ((lane>>4)&1)*8, chunk ((lane>>3)&1)
    const uint32_t bpat = (uint32_t)(((lane & 7) + ((lane >> 4) & 1) * 8) * RSTRIDE +
                                     ((lane >> 3) & 1) * 16);

    float acc[8][2][4];
    #pragma unroll
    for (int nt = 0; nt < 8; ++nt)
        #pragma unroll
        for (int mt = 0; mt < 2; ++mt)
            #pragma unroll
            for (int j = 0; j < 4; ++j) acc[nt][mt][j] = 0.f;

    // pass 0: A_hi x B_hi ; pass 1: A_hi x B_lo
    #pragma unroll
    for (int p = 0; p < 2; ++p) {
        const uint32_t bbase = sb + (p ? SM_BL : SM_BH) + (uint32_t)(ncol * RSTRIDE) + bpat;
        #pragma unroll
        for (int kk = 0; kk < 8; ++kk) {
            uint32_t a0[4], a1[4];
            ldsm_x4(a0[0], a0[1], a0[2], a0[3], aoff0 + kk * 32);
            ldsm_x4(a1[0], a1[1], a1[2], a1[3], aoff1 + kk * 32);
            #pragma unroll
            for (int nt2 = 0; nt2 < 4; ++nt2) {
                uint32_t b0, b1, b2, b3;
                ldsm_x4(b0, b1, b2, b3, bbase + nt2 * (16 * RSTRIDE) + kk * 32);
                mma16816(acc[2*nt2    ][0], a0[0], a0[1], a0[2], a0[3], b0, b1);
                mma16816(acc[2*nt2    ][1], a1[0], a1[1], a1[2], a1[3], b0, b1);
                mma16816(acc[2*nt2 + 1][0], a0[0], a0[1], a0[2], a0[3], b2, b3);
                mma16816(acc[2*nt2 + 1][1], a1[0], a1[1], a1[2], a1[3], b2, b3);
            }
        }
    }
    __syncthreads();
    // refill A with lo split
    for (int e = tid; e < 2048; e += 256) {
        int r = e >> 4, ch = e & 15;
        *reinterpret_cast<uint4*>(smem + SM_A + r * RSTRIDE + ch * 16) =
            reinterpret_cast<const uint4*>(g_x_lo + (size_t)(rowBase + r) * DIM)[ch];
    }
    __syncthreads();
    // pass 2: A_lo x B_hi
    {
        const uint32_t bbase = sb + SM_BH + (uint32_t)(ncol * RSTRIDE) + bpat;
        #pragma unroll
        for (int kk = 0; kk < 8; ++kk) {
            uint32_t a0[4], a1[4];
            ldsm_x4(a0[0], a0[1], a0[2], a0[3], aoff0 + kk * 32);
            ldsm_x4(a1[0], a1[1], a1[2], a1[3], aoff1 + kk * 32);
            #pragma unroll
            for (int nt2 = 0; nt2 < 4; ++nt2) {
                uint32_t b0, b1, b2, b3;
                ldsm_x4(b0, b1, b2, b3, bbase + nt2 * (16 * RSTRIDE) + kk * 32);
                mma16816(acc[2*nt2    ][0], a0[0], a0[1], a0[2], a0[3], b0, b1);
                mma16816(acc[2*nt2    ][1], a1[0], a1[1], a1[2], a1[3], b0, b1);
                mma16816(acc[2*nt2 + 1][0], a0[0], a0[1], a0[2], a0[3], b2, b3);
                mma16816(acc[2*nt2 + 1][1], a1[0], a1[1], a1[2], a1[3], b2, b3);
            }
        }
    }
    __syncthreads();   // all warps done reading A/B smem

    // ---- tanh(literal) -> ct[128][129] (overlaps A+BH regions) ----
    float* ct = reinterpret_cast<float*>(smem + SM_A);
    {
        const int gidr = lane >> 2;          // 0..7
        const int tig  = lane & 3;           // 0..3
        #pragma unroll
        for (int nt = 0; nt < 8; ++nt) {
            const int c0 = ncol + nt * 8 + 2 * tig;
            #pragma unroll
            for (int mt = 0; mt < 2; ++mt) {
                const int r0 = mrow + mt * 16 + gidr;
                ct[r0 * 129 + c0]           = ftanh(acc[nt][mt][0] + bs[c0]);
                ct[r0 * 129 + c0 + 1]       = ftanh(acc[nt][mt][1] + bs[c0 + 1]);
                ct[(r0 + 8) * 129 + c0]     = ftanh(acc[nt][mt][2] + bs[c0]);
                ct[(r0 + 8) * 129 + c0 + 1] = ftanh(acc[nt][mt][3] + bs[c0 + 1]);
            }
        }
    }
    __syncthreads();

    // ---- segmented reduce: conj (depths 2/4/6, ND each) -> formula ----
    for (int task = tid; task < 128 * NF; task += 256) {
        const int row = task & 127;
        const int fi  = task >> 7;
        const int cb  = (G == 0) ? ((fi >> 1) * 64 + (fi & 1) * LF) : (fi * 64);
        const float* cr = &ct[row * 129 + cb];
        float fs = 0.f;
        int off = 0;
        #pragma unroll
        for (int dd = 0; dd < 3; ++dd) {
            const int d = 2 + 2 * dd;
            #pragma unroll
            for (int c = 0; c < ND; ++c) {
                float s = 0.f;
                #pragma unroll
                for (int u = 0; u < 6; ++u)
                    if (u < d) s += cr[off + u];
                fs += ftanh(s - (float)d + 1.5f);
                off += d;
            }
        }
        g_dnnf[(size_t)(rowBase + row) * NFORM + f0g + fi] = ftanh(fs + (float)(3 * ND) - 1.5f);
    }
}

// ---------------------------------------------------------------------------
// K2: loc GEMM (SIMT fp32) -> g_loc = exp(-||(x-mu)*sigma||)
// ---------------------------------------------------------------------------
#define K2_SMEM_BYTES ((DIM * K2_M + 2 * DIM * K2_N) * 4)

__global__ __launch_bounds__(256) void k2_loc(const float* __restrict__ x) {
    extern __shared__ __align__(16) float sm2[];
    float* xsT = sm2;
    float* At  = sm2 + DIM * K2_M;
    float* Bt  = At + DIM * K2_N;

    const int rowBase = blockIdx.x * K2_M;
    const int fBase   = blockIdx.y * K2_N;
    const int tid     = threadIdx.x;

    for (int e = tid; e < K2_M * (DIM / 4); e += 256) {
        int r = e >> 5, k4 = e & 31;
        float4 v = reinterpret_cast<const float4*>(x + (size_t)(rowBase + r) * DIM)[k4];
        xsT[(k4 * 4 + 0) * K2_M + r] = v.x;
        xsT[(k4 * 4 + 1) * K2_M + r] = v.y;
        xsT[(k4 * 4 + 2) * K2_M + r] = v.z;
        xsT[(k4 * 4 + 3) * K2_M + r] = v.w;
    }
    for (int e = tid; e < DIM * K2_N; e += 256) {
        int k = e >> 6, j = e & 63;
        At[e] = g_A [k * NFORM + fBase + j];
        Bt[e] = g_Bv[k * NFORM + fBase + j];
    }
    __syncthreads();

    const int tx = tid & 15, ty = tid >> 4;
    float accA[8][4], accB[8][4];
    #pragma unroll
    for (int i = 0; i < 8; ++i)
        #pragma unroll
        for (int j = 0; j < 4; ++j) { accA[i][j] = 0.f; accB[i][j] = 0.f; }

    #pragma unroll 4
    for (int k = 0; k < DIM; ++k) {
        float4 bA = *reinterpret_cast<const float4*>(&At[(k << 6) + (tx << 2)]);
        float4 bB = *reinterpret_cast<const float4*>(&Bt[(k << 6) + (tx << 2)]);
        float4 a0 = *reinterpret_cast<const float4*>(&xsT[(k << 7) + (ty << 3)]);
        float4 a1 = *reinterpret_cast<const float4*>(&xsT[(k << 7) + (ty << 3) + 4]);
        float av[8] = {a0.x, a0.y, a0.z, a0.w, a1.x, a1.y, a1.z, a1.w};
        float bAv[4] = {bA.x, bA.y, bA.z, bA.w};
        float bBv[4] = {bB.x, bB.y, bB.z, bB.w};
        #pragma unroll
        for (int i = 0; i < 8; ++i) {
            float a = av[i], a2 = a * a;
            #pragma unroll
            for (int j = 0; j < 4; ++j) {
                accA[i][j] = fmaf(a2, bAv[j], accA[i][j]);
                accB[i][j] = fmaf(a,  bBv[j], accB[i][j]);
            }
        }
    }

    #pragma unroll
    for (int i = 0; i < 8; ++i) {
        int r = rowBase + ty * 8 + i;
        #pragma unroll
        for (int j = 0; j < 4; ++j) {
            int f = fBase + tx * 4 + j;
            float v = accA[i][j] - 2.f * accB[i][j] + __ldg(&g_c[f]);
            v = fmaxf(v, 0.f);
            g_loc[(size_t)r * NFORM + f] = __expf(-__fsqrt_rn(v));
        }
    }
}

// ---------------------------------------------------------------------------
// K3: per-row softmax(sigmoid(T)*loc) * dnnf -> out
// ---------------------------------------------------------------------------
__global__ __launch_bounds__(256) void k3_softmax(const float* __restrict__ temp,
                                                  float* __restrict__ out) {
    const int row  = blockIdx.x * 8 + (threadIdx.x >> 5);
    const int lane = threadIdx.x & 31;
    const float s = 1.f / (1.f + __expf(-temp[0]));
    const size_t base = (size_t)row * NFORM;

    float z[8];
    float m = -1e30f;
    #pragma unroll
    for (int i = 0; i < 8; ++i) {
        z[i] = s * g_loc[base + lane + (i << 5)];
        m = fmaxf(m, z[i]);
    }
    #pragma unroll
    for (int off = 16; off > 0; off >>= 1)
        m = fmaxf(m, __shfl_xor_sync(0xFFFFFFFFu, m, off));
    float e[8], sum = 0.f;
    #pragma unroll
    for (int i = 0; i < 8; ++i) { e[i] = __expf(z[i] - m); sum += e[i]; }
    #pragma unroll
    for (int off = 16; off > 0; off >>= 1)
        sum += __shfl_xor_sync(0xFFFFFFFFu, sum, off);
    const float inv = 1.f / sum;
    #pragma unroll
    for (int i = 0; i < 8; ++i) {
        size_t idx = base + lane + (i << 5);
        out[idx] = g_dnnf[idx] * e[i] * inv;
    }
}

// ---------------------------------------------------------------------------
extern "C" void kernel_launch(void* const* d_in, const int* in_sizes, int n_in,
                              void* d_out, int out_size) {
    const float* x     = (const float*)d_in[0];
    const float* w     = (const float*)d_in[1];
    const float* bias  = (const float*)d_in[2];
    const float* lm    = (const float*)d_in[3];
    const float* mu    = (const float*)d_in[4];
    const float* sigma = (const float*)d_in[5];
    const float* temp  = (const float*)d_in[6];
    float* out = (float*)d_out;

    cudaFuncSetAttribute(k1_tensor<0>, cudaFuncAttributeMaxDynamicSharedMemorySize, K1_SMEM);
    cudaFuncSetAttribute(k1_tensor<1>, cudaFuncAttributeMaxDynamicSharedMemorySize, K1_SMEM);
    cudaFuncSetAttribute(k1_tensor<2>, cudaFuncAttributeMaxDynamicSharedMemorySize, K1_SMEM);
    cudaFuncSetAttribute(k1_tensor<3>, cudaFuncAttributeMaxDynamicSharedMemorySize, K1_SMEM);
    cudaFuncSetAttribute(k2_loc,       cudaFuncAttributeMaxDynamicSharedMemorySize, K2_SMEM_BYTES);

    k0_precompute<<<NFORM, DIM>>>(mu, sigma);
    k0_split_x<<<BATCH * DIM / (256 * 8), 256>>>(x);
    k0_split_w<<<NLIT / 64, 256>>>(w, lm);
    k1_tensor<0><<<dim3(32, 16), 256, K1_SMEM>>>(bias);
    k1_tensor<1><<<dim3(32, 32), 256, K1_SMEM>>>(bias);
    k1_tensor<2><<<dim3(32, 32), 256, K1_SMEM>>>(bias);
    k1_tensor<3><<<dim3(32, 32), 256, K1_SMEM>>>(bias);
    k2_loc<<<dim3(BATCH / K2_M, NFORM / K2_N), 256, K2_SMEM_BYTES>>>(x);
    k3_softmax<<<BATCH / 8, 256>>>(temp, out);
}

// round 6
// speedup vs baseline: 6.9065x; 1.3560x over previous
#include <cuda_runtime.h>
#include <cuda_bf16.h>
#include <math.h>
#include <stdint.h>

// ---------------------------------------------------------------------------
// Problem constants
// ---------------------------------------------------------------------------
#define BATCH      4096
#define DIM        128
#define NFORM      256
#define NLIT       10752

#define K2_M       128
#define K2_N       64

// ---------------------------------------------------------------------------
// Helpers (portable PTX only: ldmatrix / mma.sync / cp.async, legal at compute_103)
// ---------------------------------------------------------------------------
__device__ __forceinline__ float ftanh(float v) {
    float r; asm("tanh.approx.f32 %0, %1;" : "=f"(r) : "f"(v)); return r;
}
__device__ __forceinline__ uint32_t smem_u32(const void* p) {
    uint32_t a;
    asm("{ .reg .u64 t; cvta.to.shared.u64 t, %1; cvt.u32.u64 %0, t; }" : "=r"(a) : "l"(p));
    return a;
}
__device__ __forceinline__ void ldsm_x4(uint32_t& r0, uint32_t& r1, uint32_t& r2, uint32_t& r3,
                                        uint32_t addr) {
    asm volatile("ldmatrix.sync.aligned.m8n8.x4.shared.b16 {%0,%1,%2,%3}, [%4];"
                 : "=r"(r0), "=r"(r1), "=r"(r2), "=r"(r3) : "r"(addr));
}
__device__ __forceinline__ void mma16816(float* c, uint32_t a0, uint32_t a1, uint32_t a2,
                                         uint32_t a3, uint32_t b0, uint32_t b1) {
    asm volatile("mma.sync.aligned.m16n8k16.row.col.f32.bf16.bf16.f32 "
                 "{%0,%1,%2,%3}, {%4,%5,%6,%7}, {%8,%9}, {%0,%1,%2,%3};"
                 : "+f"(c[0]), "+f"(c[1]), "+f"(c[2]), "+f"(c[3])
                 : "r"(a0), "r"(a1), "r"(a2), "r"(a3), "r"(b0), "r"(b1));
}
__device__ __forceinline__ void cpa16(uint32_t dst, const void* src, uint32_t srcsize) {
    asm volatile("cp.async.ca.shared.global [%0], [%1], 16, %2;"
                 :: "r"(dst), "l"(src), "r"(srcsize));
}
__device__ __forceinline__ void cpa_commit() { asm volatile("cp.async.commit_group;"); }
__device__ __forceinline__ void cpa_wait1()  { asm volatile("cp.async.wait_group 1;"); }
__device__ __forceinline__ void cpa_wait0()  { asm volatile("cp.async.wait_group 0;"); }

// ---------------------------------------------------------------------------
// Scratch (device globals)
// ---------------------------------------------------------------------------
__device__ float          g_dnnf[BATCH * NFORM];
__device__ float          g_loc [BATCH * NFORM];
__device__ float          g_A   [DIM * NFORM];
__device__ float          g_Bv  [DIM * NFORM];
__device__ float          g_c   [NFORM];
__device__ __nv_bfloat16  g_x_hi[BATCH * DIM];
__device__ __nv_bfloat16  g_x_lo[BATCH * DIM];
__device__ __nv_bfloat16  g_wt_hi[(size_t)NLIT * DIM];   // [l][k], literal-major
__device__ __nv_bfloat16  g_wt_lo[(size_t)NLIT * DIM];

// ---------------------------------------------------------------------------
// K0a: sigma^2 / mu*sigma^2 / c   (for K2)
// ---------------------------------------------------------------------------
__global__ void k0_precompute(const float* __restrict__ mu,
                              const float* __restrict__ sigma) {
    int f = blockIdx.x, k = threadIdx.x;
    float sg = sigma[f * DIM + k];
    float m  = mu[f * DIM + k];
    float s2 = sg * sg;
    float bv = m * s2;
    g_A [k * NFORM + f] = s2;
    g_Bv[k * NFORM + f] = bv;
    float cp = m * bv;
    #pragma unroll
    for (int off = 16; off > 0; off >>= 1)
        cp += __shfl_xor_sync(0xFFFFFFFFu, cp, off);
    __shared__ float red[4];
    if ((k & 31) == 0) red[k >> 5] = cp;
    __syncthreads();
    if (k == 0) g_c[f] = red[0] + red[1] + red[2] + red[3];
}

// ---------------------------------------------------------------------------
// K0b: split x into bf16 hi/lo
// ---------------------------------------------------------------------------
__device__ __forceinline__ void split2(float v0, float v1, uint32_t& hi, uint32_t& lo) {
    __nv_bfloat16 h0 = __float2bfloat16(v0), h1 = __float2bfloat16(v1);
    __nv_bfloat16 l0 = __float2bfloat16(v0 - __bfloat162float(h0));
    __nv_bfloat16 l1 = __float2bfloat16(v1 - __bfloat162float(h1));
    __nv_bfloat162 hh = __halves2bfloat162(h0, h1);
    __nv_bfloat162 ll = __halves2bfloat162(l0, l1);
    hi = *reinterpret_cast<uint32_t*>(&hh);
    lo = *reinterpret_cast<uint32_t*>(&ll);
}

__global__ __launch_bounds__(256) void k0_split_x(const float* __restrict__ x) {
    int e = blockIdx.x * 256 + threadIdx.x;
    const float4* src = reinterpret_cast<const float4*>(x) + (size_t)e * 2;
    float4 a = src[0], b = src[1];
    float v[8] = {a.x, a.y, a.z, a.w, b.x, b.y, b.z, b.w};
    uint32_t hi[4], lo[4];
    #pragma unroll
    for (int p = 0; p < 4; ++p) split2(v[2*p], v[2*p+1], hi[p], lo[p]);
    reinterpret_cast<uint4*>(g_x_hi)[e] = make_uint4(hi[0], hi[1], hi[2], hi[3]);
    reinterpret_cast<uint4*>(g_x_lo)[e] = make_uint4(lo[0], lo[1], lo[2], lo[3]);
}

// ---------------------------------------------------------------------------
// K0c: masked W -> transposed (literal-major) bf16 hi/lo
// ---------------------------------------------------------------------------
__global__ __launch_bounds__(256) void k0_split_w(const float* __restrict__ w,
                                                  const float* __restrict__ lm) {
    __shared__ float s[128 * 65];
    const int l0  = blockIdx.x * 64;
    const int tid = threadIdx.x;
    for (int e = tid; e < 128 * 64; e += 256) {
        int k = e >> 6, j = e & 63;
        int l = l0 + j;
        int f;
        if      (l < 1536) f = l / 24;
        else if (l < 3840) f = 64  + (l - 1536) / 36;
        else if (l < 6912) f = 128 + (l - 3840) / 48;
        else               f = 192 + (l - 6912) / 60;
        float mk = (fabsf(lm[k * NFORM + f]) > 1.0f) ? 1.0f : 0.0f;
        s[k * 65 + j] = w[(size_t)k * NLIT + l] * mk;
    }
    __syncthreads();
    for (int e = tid; e < 64 * 16; e += 256) {
        int row = e >> 4, chunk = e & 15;
        uint32_t hi[4], lo[4];
        #pragma unroll
        for (int p = 0; p < 4; ++p)
            split2(s[(chunk * 8 + 2*p) * 65 + row], s[(chunk * 8 + 2*p + 1) * 65 + row],
                   hi[p], lo[p]);
        size_t l = l0 + row;
        reinterpret_cast<uint4*>(g_wt_hi + l * DIM)[chunk] = make_uint4(hi[0], hi[1], hi[2], hi[3]);
        reinterpret_cast<uint4*>(g_wt_lo + l * DIM)[chunk] = make_uint4(lo[0], lo[1], lo[2], lo[3]);
    }
}

// ---------------------------------------------------------------------------
// K1: merged HMMA literal GEMM, virtual K=384 (hi*hi + lo*hi + hi*lo) with
//     2-stage cp.async pipeline; fused tanh + conj/formula reduce epilogue.
//   CTA: M=128 x N=128 (two 64-blocks of one group), 8 warps (4M x 2N).
// ---------------------------------------------------------------------------
#define RS       144                         // smem row stride bytes (64 bf16 + pad)
#define SM_BIAS  0                           // 128 floats
#define SA0      1024
#define SA1      (SA0 + 128 * RS)            // 19456
#define SB0      (SA1 + 128 * RS)            // 37888
#define SB1      (SB0 + 128 * RS)            // 56320
#define K1_SMEM  (SB1 + 128 * RS)            // 74752

__device__ __forceinline__ void k1_prefetch(int kc, uint32_t sa, uint32_t sbb,
                                            int tid, int rowBase,
                                            int lb0, int lb1, int BLIT) {
    const __nv_bfloat16* xsrc = (kc == 2 || kc == 3) ? g_x_lo : g_x_hi;
    const __nv_bfloat16* wsrc = (kc >= 4) ? g_wt_lo : g_wt_hi;
    const int koff = (kc & 1) * 64;
    #pragma unroll
    for (int i = 0; i < 4; ++i) {
        int e = tid + i * 256;
        int r = e >> 3, ch = e & 7;
        cpa16(sa + r * RS + ch * 16,
              xsrc + (size_t)(rowBase + r) * DIM + koff + ch * 8, 16);
    }
    #pragma unroll
    for (int i = 0; i < 4; ++i) {
        int e = tid + i * 256;
        int n = e >> 3, ch = e & 7;
        int j = n & 63;
        int lb = (n < 64) ? lb0 : lb1;
        cpa16(sbb + n * RS + ch * 16,
              wsrc + (size_t)(lb + j) * DIM + koff + ch * 8,
              (j < BLIT) ? 16u : 0u);
    }
}

__device__ __forceinline__ void k1_mma_chunk(float (&acc)[8][2][4],
                                             uint32_t sa, uint32_t sbb,
                                             uint32_t apat0, uint32_t apat1,
                                             uint32_t bpat) {
    #pragma unroll
    for (int kk = 0; kk < 4; ++kk) {
        uint32_t a0[4], a1[4];
        ldsm_x4(a0[0], a0[1], a0[2], a0[3], sa + apat0 + kk * 32);
        ldsm_x4(a1[0], a1[1], a1[2], a1[3], sa + apat1 + kk * 32);
        #pragma unroll
        for (int nt2 = 0; nt2 < 4; ++nt2) {
            uint32_t b0, b1, b2, b3;
            ldsm_x4(b0, b1, b2, b3, sbb + bpat + nt2 * (16 * RS) + kk * 32);
            mma16816(acc[2*nt2    ][0], a0[0], a0[1], a0[2], a0[3], b0, b1);
            mma16816(acc[2*nt2    ][1], a1[0], a1[1], a1[2], a1[3], b0, b1);
            mma16816(acc[2*nt2 + 1][0], a0[0], a0[1], a0[2], a0[3], b2, b3);
            mma16816(acc[2*nt2 + 1][1], a1[0], a1[1], a1[2], a1[3], b2, b3);
        }
    }
}

__global__ __launch_bounds__(256, 2) void k1_tensor(const float* __restrict__ bias) {
    extern __shared__ __align__(1024) char smem[];
    const uint32_t sb = smem_u32(smem);
    float* bs = reinterpret_cast<float*>(smem + SM_BIAS);

    const int tid     = threadIdx.x;
    const int wid     = tid >> 5;
    const int lane    = tid & 31;
    const int rowBase = blockIdx.x * 128;

    // ---- runtime group decode (y-tile -> formulas / literal layout) ----
    const int yy = blockIdx.y;
    int nft, BLIT, f0g, lb0, nd;
    if (yy < 16)      { nft = 2; BLIT = 48; nd = 2; f0g = 4 * yy;                lb0 = 96 * yy; }
    else if (yy < 48) { int t = yy - 16; nft = 1; BLIT = 36; nd = 3; f0g = 64  + 2 * t; lb0 = 1536 + 72 * t; }
    else if (yy < 80) { int t = yy - 48; nft = 1; BLIT = 48; nd = 4; f0g = 128 + 2 * t; lb0 = 3840 + 96 * t; }
    else              { int t = yy - 80; nft = 1; BLIT = 60; nd = 5; f0g = 192 + 2 * t; lb0 = 6912 + 120 * t; }
    const int lb1 = lb0 + BLIT;

    // ---- bias to smem ----
    if (tid < 128) {
        int j = tid & 63;
        bs[tid] = (j < BLIT) ? bias[((tid < 64) ? lb0 : lb1) + j] : 0.f;
    }

    // ---- pipeline: prefetch chunks 0,1 ----
    k1_prefetch(0, sb + SA0, sb + SB0, tid, rowBase, lb0, lb1, BLIT);
    cpa_commit();
    k1_prefetch(1, sb + SA1, sb + SB1, tid, rowBase, lb0, lb1, BLIT);
    cpa_commit();

    // warp grid 4(M) x 2(N)
    const int mrow = (wid & 3) * 32;
    const int ncol = (wid >> 2) * 64;
    const uint32_t apat0 = (uint32_t)((mrow + (lane & 15)) * RS + (lane >> 4) * 16);
    const uint32_t apat1 = apat0 + 16 * RS;
    const uint32_t bpat  = (uint32_t)(ncol * RS +
                           ((lane & 7) + ((lane >> 4) & 1) * 8) * RS + ((lane >> 3) & 1) * 16);

    float acc[8][2][4];
    #pragma unroll
    for (int nt = 0; nt < 8; ++nt)
        #pragma unroll
        for (int mt = 0; mt < 2; ++mt)
            #pragma unroll
            for (int j = 0; j < 4; ++j) acc[nt][mt][j] = 0.f;

    // ---- mainloop over 6 virtual-K chunks ----
    #pragma unroll
    for (int kc = 0; kc < 6; ++kc) {
        if (kc < 5) cpa_wait1(); else cpa_wait0();
        __syncthreads();
        const uint32_t sa  = sb + ((kc & 1) ? SA1 : SA0);
        const uint32_t sbb = sb + ((kc & 1) ? SB1 : SB0);
        k1_mma_chunk(acc, sa, sbb, apat0, apat1, bpat);
        if (kc < 4) {
            __syncthreads();                 // stage free before overwrite
            k1_prefetch(kc + 2, sa, sbb, tid, rowBase, lb0, lb1, BLIT);
            cpa_commit();
        }
    }
    __syncthreads();                         // all warps done with smem stages

    // ---- tanh(literal) -> ct[128][129] (reuses stage smem) ----
    float* ct = reinterpret_cast<float*>(smem + SA0);
    {
        const int gidr = lane >> 2;
        const int tig  = lane & 3;
        #pragma unroll
        for (int nt = 0; nt < 8; ++nt) {
            const int c0 = ncol + nt * 8 + 2 * tig;
            #pragma unroll
            for (int mt = 0; mt < 2; ++mt) {
                const int r0 = mrow + mt * 16 + gidr;
                ct[r0 * 129 + c0]           = ftanh(acc[nt][mt][0] + bs[c0]);
                ct[r0 * 129 + c0 + 1]       = ftanh(acc[nt][mt][1] + bs[c0 + 1]);
                ct[(r0 + 8) * 129 + c0]     = ftanh(acc[nt][mt][2] + bs[c0]);
                ct[(r0 + 8) * 129 + c0 + 1] = ftanh(acc[nt][mt][3] + bs[c0 + 1]);
            }
        }
    }
    __syncthreads();

    // ---- segmented reduce: nd conjs each of depth 2/4/6 -> formula ----
    const int nf = 2 * nft;
    for (int task = tid; task < 128 * nf; task += 256) {
        const int row = task & 127;
        const int fi  = task >> 7;
        const int cb  = (nft == 2) ? ((fi >> 1) * 64 + (fi & 1) * 24) : (fi * 64);
        const float* cr = &ct[row * 129 + cb];
        float fs = 0.f;
        int off = 0;
        #pragma unroll
        for (int dd = 0; dd < 3; ++dd) {
            const int d = 2 + 2 * dd;
            for (int c = 0; c < nd; ++c) {
                float s = 0.f;
                #pragma unroll
                for (int u = 0; u < 6; ++u)
                    if (u < d) s += cr[off + u];
                fs += ftanh(s - (float)d + 1.5f);
                off += d;
            }
        }
        g_dnnf[(size_t)(rowBase + row) * NFORM + f0g + fi] =
            ftanh(fs + 3.0f * (float)nd - 1.5f);
    }
}

// ---------------------------------------------------------------------------
// K2: loc GEMM (SIMT fp32) -> g_loc = exp(-||(x-mu)*sigma||)
// ---------------------------------------------------------------------------
#define K2_SMEM_BYTES ((DIM * K2_M + 2 * DIM * K2_N) * 4)

__global__ __launch_bounds__(256) void k2_loc(const float* __restrict__ x) {
    extern __shared__ __align__(16) float sm2[];
    float* xsT = sm2;
    float* At  = sm2 + DIM * K2_M;
    float* Bt  = At + DIM * K2_N;

    const int rowBase = blockIdx.x * K2_M;
    const int fBase   = blockIdx.y * K2_N;
    const int tid     = threadIdx.x;

    for (int e = tid; e < K2_M * (DIM / 4); e += 256) {
        int r = e >> 5, k4 = e & 31;
        float4 v = reinterpret_cast<const float4*>(x + (size_t)(rowBase + r) * DIM)[k4];
        xsT[(k4 * 4 + 0) * K2_M + r] = v.x;
        xsT[(k4 * 4 + 1) * K2_M + r] = v.y;
        xsT[(k4 * 4 + 2) * K2_M + r] = v.z;
        xsT[(k4 * 4 + 3) * K2_M + r] = v.w;
    }
    for (int e = tid; e < DIM * K2_N; e += 256) {
        int k = e >> 6, j = e & 63;
        At[e] = g_A [k * NFORM + fBase + j];
        Bt[e] = g_Bv[k * NFORM + fBase + j];
    }
    __syncthreads();

    const int tx = tid & 15, ty = tid >> 4;
    float accA[8][4], accB[8][4];
    #pragma unroll
    for (int i = 0; i < 8; ++i)
        #pragma unroll
        for (int j = 0; j < 4; ++j) { accA[i][j] = 0.f; accB[i][j] = 0.f; }

    #pragma unroll 4
    for (int k = 0; k < DIM; ++k) {
        float4 bA = *reinterpret_cast<const float4*>(&At[(k << 6) + (tx << 2)]);
        float4 bB = *reinterpret_cast<const float4*>(&Bt[(k << 6) + (tx << 2)]);
        float4 a0 = *reinterpret_cast<const float4*>(&xsT[(k << 7) + (ty << 3)]);
        float4 a1 = *reinterpret_cast<const float4*>(&xsT[(k << 7) + (ty << 3) + 4]);
        float av[8] = {a0.x, a0.y, a0.z, a0.w, a1.x, a1.y, a1.z, a1.w};
        float bAv[4] = {bA.x, bA.y, bA.z, bA.w};
        float bBv[4] = {bB.x, bB.y, bB.z, bB.w};
        #pragma unroll
        for (int i = 0; i < 8; ++i) {
            float a = av[i], a2 = a * a;
            #pragma unroll
            for (int j = 0; j < 4; ++j) {
                accA[i][j] = fmaf(a2, bAv[j], accA[i][j]);
                accB[i][j] = fmaf(a,  bBv[j], accB[i][j]);
            }
        }
    }

    #pragma unroll
    for (int i = 0; i < 8; ++i) {
        int r = rowBase + ty * 8 + i;
        #pragma unroll
        for (int j = 0; j < 4; ++j) {
            int f = fBase + tx * 4 + j;
            float v = accA[i][j] - 2.f * accB[i][j] + __ldg(&g_c[f]);
            v = fmaxf(v, 0.f);
            g_loc[(size_t)r * NFORM + f] = __expf(-__fsqrt_rn(v));
        }
    }
}

// ---------------------------------------------------------------------------
// K3: per-row softmax(sigmoid(T)*loc) * dnnf -> out
// ---------------------------------------------------------------------------
__global__ __launch_bounds__(256) void k3_softmax(const float* __restrict__ temp,
                                                  float* __restrict__ out) {
    const int row  = blockIdx.x * 8 + (threadIdx.x >> 5);
    const int lane = threadIdx.x & 31;
    const float s = 1.f / (1.f + __expf(-temp[0]));
    const size_t base = (size_t)row * NFORM;

    float z[8];
    float m = -1e30f;
    #pragma unroll
    for (int i = 0; i < 8; ++i) {
        z[i] = s * g_loc[base + lane + (i << 5)];
        m = fmaxf(m, z[i]);
    }
    #pragma unroll
    for (int off = 16; off > 0; off >>= 1)
        m = fmaxf(m, __shfl_xor_sync(0xFFFFFFFFu, m, off));
    float e[8], sum = 0.f;
    #pragma unroll
    for (int i = 0; i < 8; ++i) { e[i] = __expf(z[i] - m); sum += e[i]; }
    #pragma unroll
    for (int off = 16; off > 0; off >>= 1)
        sum += __shfl_xor_sync(0xFFFFFFFFu, sum, off);
    const float inv = 1.f / sum;
    #pragma unroll
    for (int i = 0; i < 8; ++i) {
        size_t idx = base + lane + (i << 5);
        out[idx] = g_dnnf[idx] * e[i] * inv;
    }
}

// ---------------------------------------------------------------------------
extern "C" void kernel_launch(void* const* d_in, const int* in_sizes, int n_in,
                              void* d_out, int out_size) {
    const float* x     = (const float*)d_in[0];
    const float* w     = (const float*)d_in[1];
    const float* bias  = (const float*)d_in[2];
    const float* lm    = (const float*)d_in[3];
    const float* mu    = (const float*)d_in[4];
    const float* sigma = (const float*)d_in[5];
    const float* temp  = (const float*)d_in[6];
    float* out = (float*)d_out;

    cudaFuncSetAttribute(k1_tensor, cudaFuncAttributeMaxDynamicSharedMemorySize, K1_SMEM);
    cudaFuncSetAttribute(k2_loc,    cudaFuncAttributeMaxDynamicSharedMemorySize, K2_SMEM_BYTES);

    k0_precompute<<<NFORM, DIM>>>(mu, sigma);
    k0_split_x<<<BATCH * DIM / (256 * 8), 256>>>(x);
    k0_split_w<<<NLIT / 64, 256>>>(w, lm);
    k1_tensor<<<dim3(32, 112), 256, K1_SMEM>>>(bias);
    k2_loc<<<dim3(BATCH / K2_M, NFORM / K2_N), 256, K2_SMEM_BYTES>>>(x);
    k3_softmax<<<BATCH / 8, 256>>>(temp, out);
}